// round 13
// baseline (speedup 1.0000x reference)
#include <cuda_runtime.h>
#include <math.h>
#include <stdint.h>

#define B_ROWS 2048
#define D_DIM  512
#define C_CLS  32768
#define S_SCALE 64.0f
#define SQRT_S 8.0f
#define MARGIN  0.5f
#define EPS_CLIP 1e-7f

#define BM 128
#define BN 256
#define NCH 4                    // 512 / 128 bytes per chunk
#define A_STAGE 16384            // 128 rows x 128 B
#define B_STAGE 32768            // 256 rows x 128 B
#define STAGE_BYTES (A_STAGE + B_STAGE)   // 49152
#define NSTAGE 3
#define SMEM_TOTAL (NSTAGE * STAGE_BYTES) // 147456 (1 CTA/SM, 16 warps)

// prep grid split (8 warps = 8 rows per block)
#define PREP_W_BLOCKS  (C_CLS / 8)             // 4096
#define PREP_F_BLOCKS  (B_ROWS / 8)            // 256
#define PREP_T_BLOCKS  (B_ROWS / 8)            // 256
#define PREP_BLOCKS    (PREP_W_BLOCKS + PREP_F_BLOCKS + PREP_T_BLOCKS)

// ---------------------------------------------------------------------------
__device__ float  g_rowsum[B_ROWS];
__device__ float  g_tgt[B_ROWS];
__device__ __align__(16) uint8_t g_F8[B_ROWS * D_DIM];   // e4m3(8 * f_hat)
__device__ __align__(16) uint8_t g_W8[C_CLS * D_DIM];    // e4m3(8 * w_hat)

// ---------------------------------------------------------------------------
__device__ __forceinline__ uint32_t smem_u32(const void* p) {
    uint32_t a;
    asm("{ .reg .u64 t; cvta.to.shared.u64 t, %1; cvt.u32.u64 %0, t; }" : "=r"(a) : "l"(p));
    return a;
}

__device__ __forceinline__ void mma_f8(float* c, const uint4& a,
                                       uint32_t b0, uint32_t b1) {
    asm volatile(
        "mma.sync.aligned.m16n8k32.row.col.f32.e4m3.e4m3.f32 "
        "{%0,%1,%2,%3}, {%4,%5,%6,%7}, {%8,%9}, {%0,%1,%2,%3};"
        : "+f"(c[0]), "+f"(c[1]), "+f"(c[2]), "+f"(c[3])
        : "r"(a.x), "r"(a.y), "r"(a.z), "r"(a.w), "r"(b0), "r"(b1));
}

__device__ __forceinline__ void ldsm4(uint4& d, uint32_t a) {
    asm volatile("ldmatrix.sync.aligned.m8n8.x4.shared.b16 {%0,%1,%2,%3}, [%4];"
                 : "=r"(d.x), "=r"(d.y), "=r"(d.z), "=r"(d.w) : "r"(a));
}

__device__ __forceinline__ void cpasync16(uint32_t dst, const void* src) {
    asm volatile("cp.async.cg.shared.global [%0], [%1], 16;" :: "r"(dst), "l"(src));
}
#define CP_COMMIT asm volatile("cp.async.commit_group;" ::: "memory")
#define CP_WAIT1  asm volatile("cp.async.wait_group 1;" ::: "memory")
#define CP_WAIT0  asm volatile("cp.async.wait_group 0;" ::: "memory")

__device__ __forceinline__ uint32_t pack_e4m3x2(float lo, float hi) {
    uint16_t r;
    asm("cvt.rn.satfinite.e4m3x2.f32 %0, %1, %2;" : "=h"(r) : "f"(hi), "f"(lo));
    return (uint32_t)r;
}
__device__ __forceinline__ uint32_t pack_e4m3x4(float a, float b, float c, float d) {
    return pack_e4m3x2(a, b) | (pack_e4m3x2(c, d) << 16);
}

// ---------------------------------------------------------------------------
// Fused prep (proven):
//   blocks [0, 4096)    : W rows -> g_W8 = e4m3(8 * w_hat)
//   blocks [4096, 4352) : F rows -> g_F8 = e4m3(8 * f_hat), zero g_rowsum
//   blocks [4352, 4608) : target cosine (exact fp32, self-contained)
__global__ void prep_kernel(const float* __restrict__ F,
                            const int* __restrict__ Y,
                            const float* __restrict__ W) {
    const int bid  = blockIdx.x;
    const int warp = threadIdx.x >> 5;
    const int lane = threadIdx.x & 31;

    if (bid < PREP_W_BLOCKS + PREP_F_BLOCKS) {
        const bool isW = bid < PREP_W_BLOCKS;
        int row = isW ? (bid * 8 + warp) : ((bid - PREP_W_BLOCKS) * 8 + warp);
        const float* src = isW ? W : F;
        if (!isW && lane == 0) g_rowsum[row] = 0.0f;
        const float4* p = (const float4*)(src + (size_t)row * D_DIM);
        float4 v[4]; float ss = 0.0f;
#pragma unroll
        for (int i = 0; i < 4; i++) {
            v[i] = p[lane + 32 * i];
            ss = fmaf(v[i].x, v[i].x, fmaf(v[i].y, v[i].y, fmaf(v[i].z, v[i].z, fmaf(v[i].w, v[i].w, ss))));
        }
#pragma unroll
        for (int o = 16; o; o >>= 1) ss += __shfl_xor_sync(0xffffffffu, ss, o);
        float sc = SQRT_S / fmaxf(sqrtf(ss), 1e-12f);
        uint8_t* dst = isW ? g_W8 : g_F8;
        uint32_t* o32 = (uint32_t*)(dst + (size_t)row * D_DIM);
        o32[lane +  0] = pack_e4m3x4(v[0].x * sc, v[0].y * sc, v[0].z * sc, v[0].w * sc);
        o32[lane + 32] = pack_e4m3x4(v[1].x * sc, v[1].y * sc, v[1].z * sc, v[1].w * sc);
        o32[lane + 64] = pack_e4m3x4(v[2].x * sc, v[2].y * sc, v[2].z * sc, v[2].w * sc);
        o32[lane + 96] = pack_e4m3x4(v[3].x * sc, v[3].y * sc, v[3].z * sc, v[3].w * sc);
    } else {
        int row = (bid - PREP_W_BLOCKS - PREP_F_BLOCKS) * 8 + warp;
        int cls = Y[row];
        const float4* fp = (const float4*)(F + (size_t)row * D_DIM);
        const float4* wp = (const float4*)(W + (size_t)cls * D_DIM);
        float dot = 0.0f, ff = 0.0f, ww = 0.0f;
#pragma unroll
        for (int i = 0; i < 4; i++) {
            float4 a = fp[lane + 32 * i];
            float4 b = wp[lane + 32 * i];
            dot = fmaf(a.x, b.x, fmaf(a.y, b.y, fmaf(a.z, b.z, fmaf(a.w, b.w, dot))));
            ff  = fmaf(a.x, a.x, fmaf(a.y, a.y, fmaf(a.z, a.z, fmaf(a.w, a.w, ff))));
            ww  = fmaf(b.x, b.x, fmaf(b.y, b.y, fmaf(b.z, b.z, fmaf(b.w, b.w, ww))));
        }
#pragma unroll
        for (int o = 16; o; o >>= 1) {
            dot += __shfl_xor_sync(0xffffffffu, dot, o);
            ff  += __shfl_xor_sync(0xffffffffu, ff,  o);
            ww  += __shfl_xor_sync(0xffffffffu, ww,  o);
        }
        if (lane == 0)
            g_tgt[row] = dot / (fmaxf(sqrtf(ff), 1e-12f) * fmaxf(sqrtf(ww), 1e-12f));
    }
}

// ---------------------------------------------------------------------------
// fp8 mma GEMM: 128x256 CTA tile, 512 threads (16 warps, 1 CTA/SM),
// 3-stage cp.async ring of k128 chunks (48KB stages), one barrier per chunk,
// prefetch-before-compute. Per-warp microkernel identical to the proven R10.
// stage layout: A 128x128B at +0, B 256x128B at +16384.
// swizzle: 16B col j stored at j ^ (row & 7).
__global__ void __launch_bounds__(512, 1)
gemm_exp_mma_kernel() {
    extern __shared__ __align__(16) char smb[];   // 3 * 48KB
    const uint32_t smbase = smem_u32(smb);
    const int tid  = threadIdx.x;
    const int lane = tid & 31;
    const int warp = tid >> 5;
    const int wm = warp >> 3;          // 0..1   (m half)
    const int wn = warp & 7;           // 0..7   (n eighth of 256)
    const int tm = blockIdx.y;
    const int tn = blockIdx.x;

    // ---- cp.async setup: per thread 2x16B of A + 4x16B of B per chunk ----
    const int jj = tid & 7;            // 16B column
    const int r0 = tid >> 3;           // base row 0..63
    const uint32_t dA = (uint32_t)(r0 * 128 + ((jj ^ (r0 & 7)) << 4));
    // rows r0+64k share (row&7) -> same swizzle, +8192 per 64 rows
    const uint8_t* sA = g_F8 + (size_t)(tm * BM + r0) * D_DIM + jj * 16;
    const uint8_t* sB = g_W8 + (size_t)(tn * BN + r0) * D_DIM + jj * 16;

    // ---- ldmatrix lane addressing (same derivation as R10) ----
    const int l15 = lane & 15, xorl = lane & 7, hi = lane >> 4;
    uint32_t xk[4];
#pragma unroll
    for (int ks = 0; ks < 4; ks++)
        xk[ks] = (uint32_t)((((ks << 1) | hi) ^ xorl) << 4);
    const uint32_t aBase = smbase + ((wm * 64 + l15) << 7);
    const uint32_t bBase = smbase + A_STAGE + ((wn * 32 + l15) << 7);

    float acc[4][4][4];
#pragma unroll
    for (int a = 0; a < 4; a++)
#pragma unroll
        for (int b = 0; b < 4; b++)
#pragma unroll
            for (int c = 0; c < 4; c++) acc[a][b][c] = 0.0f;

    // ---- prologue: prefetch chunks 0 and 1 into stages 0 and 1 ----
#pragma unroll
    for (int s = 0; s < 2; s++) {
        const uint32_t st = smbase + s * STAGE_BYTES;
        const uint8_t* pa = sA + s * 128;
        const uint8_t* pb = sB + s * 128;
        cpasync16(st + dA,        pa);
        cpasync16(st + dA + 8192, pa + 32768);
#pragma unroll
        for (int i = 0; i < 4; i++)
            cpasync16(st + A_STAGE + dA + i * 8192, pb + i * 32768);
        CP_COMMIT;
    }

#pragma unroll
    for (int c = 0; c < NCH; c++) {
        if (c < NCH - 1) { CP_WAIT1; } else { CP_WAIT0; }
        __syncthreads();   // chunk c resident; stage (c+2)%3's readers done (iter c-1)
        if (c + 2 < NCH) { // prefetch chunk c+2 into stage (c+2)%3, overlaps compute
            const uint32_t st = smbase + ((c + 2) % NSTAGE) * STAGE_BYTES;
            const uint8_t* pa = sA + (c + 2) * 128;
            const uint8_t* pb = sB + (c + 2) * 128;
            cpasync16(st + dA,        pa);
            cpasync16(st + dA + 8192, pa + 32768);
#pragma unroll
            for (int i = 0; i < 4; i++)
                cpasync16(st + A_STAGE + dA + i * 8192, pb + i * 32768);
            CP_COMMIT;
        }
        const uint32_t bo = (uint32_t)(c % NSTAGE) * STAGE_BYTES;
#pragma unroll
        for (int ks = 0; ks < 4; ks++) {
            uint4 afr[4], b0, b1;
#pragma unroll
            for (int mt = 0; mt < 4; mt++)
                ldsm4(afr[mt], aBase + bo + (mt << 11) + xk[ks]);
            ldsm4(b0, bBase + bo + xk[ks]);
            ldsm4(b1, bBase + bo + (1 << 11) + xk[ks]);
#pragma unroll
            for (int mt = 0; mt < 4; mt++) {
                mma_f8(acc[mt][0], afr[mt], b0.x, b0.z);
                mma_f8(acc[mt][1], afr[mt], b0.y, b0.w);
                mma_f8(acc[mt][2], afr[mt], b1.x, b1.z);
                mma_f8(acc[mt][3], afr[mt], b1.y, b1.w);
            }
        }
    }

    // ---- epilogue: exp + row reduce + atomicAdd ----
    float s[4][2];
#pragma unroll
    for (int mt = 0; mt < 4; mt++) {
        float s0 = 0.0f, s1 = 0.0f;
#pragma unroll
        for (int nt = 0; nt < 4; nt++) {
            s0 += __expf(acc[mt][nt][0]) + __expf(acc[mt][nt][1]);
            s1 += __expf(acc[mt][nt][2]) + __expf(acc[mt][nt][3]);
        }
        s[mt][0] = s0; s[mt][1] = s1;
    }
#pragma unroll
    for (int o = 1; o < 4; o <<= 1)
#pragma unroll
        for (int mt = 0; mt < 4; mt++) {
            s[mt][0] += __shfl_xor_sync(0xffffffffu, s[mt][0], o);
            s[mt][1] += __shfl_xor_sync(0xffffffffu, s[mt][1], o);
        }
    if ((lane & 3) == 0) {
        int g = lane >> 2;
        int base = tm * BM + wm * 64 + g;
#pragma unroll
        for (int mt = 0; mt < 4; mt++) {
            atomicAdd(&g_rowsum[base + mt * 16],     s[mt][0]);
            atomicAdd(&g_rowsum[base + mt * 16 + 8], s[mt][1]);
        }
    }
}

// ---------------------------------------------------------------------------
__global__ void loss_kernel(float* __restrict__ out) {
    __shared__ double sh[1024];
    double a = 0.0;
    for (int b = threadIdx.x; b < B_ROWS; b += blockDim.x) {
        float t = fminf(fmaxf(g_tgt[b], -1.0f + EPS_CLIP), 1.0f - EPS_CLIP);
        float num = S_SCALE * cosf(acosf(t) + MARGIN);
        float excl = g_rowsum[b] - __expf(S_SCALE * t);
        double denom = (double)__expf(num) + (double)excl;
        a += (double)num - log(denom);
    }
    sh[threadIdx.x] = a;
    __syncthreads();
    for (int s = 512; s > 0; s >>= 1) {
        if (threadIdx.x < s) sh[threadIdx.x] += sh[threadIdx.x + s];
        __syncthreads();
    }
    if (threadIdx.x == 0) out[0] = (float)(-sh[0] / (double)B_ROWS);
}

// ---------------------------------------------------------------------------
extern "C" void kernel_launch(void* const* d_in, const int* in_sizes, int n_in,
                              void* d_out, int out_size) {
    const float* F = (const float*)d_in[0];
    const int*   Y = (const int*)d_in[1];
    const float* W = (const float*)d_in[2];
    float* out = (float*)d_out;

    cudaFuncSetAttribute(gemm_exp_mma_kernel,
                         cudaFuncAttributeMaxDynamicSharedMemorySize, SMEM_TOTAL);

    prep_kernel<<<PREP_BLOCKS, 256>>>(F, Y, W);

    dim3 grid(C_CLS / BN, B_ROWS / BM);   // (128, 16)
    gemm_exp_mma_kernel<<<grid, 512, SMEM_TOTAL>>>();

    loss_kernel<<<1, 1024>>>(out);
}

// round 14
// speedup vs baseline: 1.0455x; 1.0455x over previous
#include <cuda_runtime.h>
#include <math.h>
#include <stdint.h>

#define B_ROWS 2048
#define D_DIM  512
#define C_CLS  32768
#define S_SCALE 64.0f
#define SQRT_S 8.0f
#define MARGIN  0.5f
#define EPS_CLIP 1e-7f

#define BM 128
#define BN 128
#define BUF_BYTES 32768          // A 16KB + B 16KB per stage
#define B_REGION  16384
#define SMEM_TOTAL (2 * BUF_BYTES)
#define N_TILES_M (B_ROWS / BM)   // 16
#define N_TILES_N (C_CLS / BN)    // 256
#define NTILES    (N_TILES_M * N_TILES_N)  // 4096
#define GRIDP     296             // persistent CTAs (2 per SM on 148 SMs)

// prep grid split (8 warps = 8 rows per block)
#define PREP_W_BLOCKS  (C_CLS / 8)             // 4096
#define PREP_F_BLOCKS  (B_ROWS / 8)            // 256
#define PREP_T_BLOCKS  (B_ROWS / 8)            // 256
#define PREP_BLOCKS    (PREP_W_BLOCKS + PREP_F_BLOCKS + PREP_T_BLOCKS)

// ---------------------------------------------------------------------------
__device__ float  g_rowsum[B_ROWS];
__device__ float  g_tgt[B_ROWS];
__device__ __align__(16) uint8_t g_F8[B_ROWS * D_DIM];   // e4m3(8 * f_hat)
__device__ __align__(16) uint8_t g_W8[C_CLS * D_DIM];    // e4m3(8 * w_hat)

// ---------------------------------------------------------------------------
__device__ __forceinline__ uint32_t smem_u32(const void* p) {
    uint32_t a;
    asm("{ .reg .u64 t; cvta.to.shared.u64 t, %1; cvt.u32.u64 %0, t; }" : "=r"(a) : "l"(p));
    return a;
}

__device__ __forceinline__ void mma_f8(float* c, const uint4& a,
                                       uint32_t b0, uint32_t b1) {
    asm volatile(
        "mma.sync.aligned.m16n8k32.row.col.f32.e4m3.e4m3.f32 "
        "{%0,%1,%2,%3}, {%4,%5,%6,%7}, {%8,%9}, {%0,%1,%2,%3};"
        : "+f"(c[0]), "+f"(c[1]), "+f"(c[2]), "+f"(c[3])
        : "r"(a.x), "r"(a.y), "r"(a.z), "r"(a.w), "r"(b0), "r"(b1));
}

__device__ __forceinline__ void ldsm4(uint4& d, uint32_t a) {
    asm volatile("ldmatrix.sync.aligned.m8n8.x4.shared.b16 {%0,%1,%2,%3}, [%4];"
                 : "=r"(d.x), "=r"(d.y), "=r"(d.z), "=r"(d.w) : "r"(a));
}

__device__ __forceinline__ void cpasync16(uint32_t dst, const void* src) {
    asm volatile("cp.async.cg.shared.global [%0], [%1], 16;" :: "r"(dst), "l"(src));
}
#define CP_COMMIT asm volatile("cp.async.commit_group;" ::: "memory")
#define CP_WAIT1  asm volatile("cp.async.wait_group 1;" ::: "memory")
#define CP_WAIT0  asm volatile("cp.async.wait_group 0;" ::: "memory")

__device__ __forceinline__ uint32_t pack_e4m3x2(float lo, float hi) {
    uint16_t r;
    asm("cvt.rn.satfinite.e4m3x2.f32 %0, %1, %2;" : "=h"(r) : "f"(hi), "f"(lo));
    return (uint32_t)r;
}
__device__ __forceinline__ uint32_t pack_e4m3x4(float a, float b, float c, float d) {
    return pack_e4m3x2(a, b) | (pack_e4m3x2(c, d) << 16);
}

// ---------------------------------------------------------------------------
// Fused prep (proven):
//   blocks [0, 4096)    : W rows -> g_W8 = e4m3(8 * w_hat)
//   blocks [4096, 4352) : F rows -> g_F8 = e4m3(8 * f_hat), zero g_rowsum
//   blocks [4352, 4608) : target cosine (exact fp32, self-contained)
__global__ void prep_kernel(const float* __restrict__ F,
                            const int* __restrict__ Y,
                            const float* __restrict__ W) {
    const int bid  = blockIdx.x;
    const int warp = threadIdx.x >> 5;
    const int lane = threadIdx.x & 31;

    if (bid < PREP_W_BLOCKS + PREP_F_BLOCKS) {
        const bool isW = bid < PREP_W_BLOCKS;
        int row = isW ? (bid * 8 + warp) : ((bid - PREP_W_BLOCKS) * 8 + warp);
        const float* src = isW ? W : F;
        if (!isW && lane == 0) g_rowsum[row] = 0.0f;
        const float4* p = (const float4*)(src + (size_t)row * D_DIM);
        float4 v[4]; float ss = 0.0f;
#pragma unroll
        for (int i = 0; i < 4; i++) {
            v[i] = p[lane + 32 * i];
            ss = fmaf(v[i].x, v[i].x, fmaf(v[i].y, v[i].y, fmaf(v[i].z, v[i].z, fmaf(v[i].w, v[i].w, ss))));
        }
#pragma unroll
        for (int o = 16; o; o >>= 1) ss += __shfl_xor_sync(0xffffffffu, ss, o);
        float sc = SQRT_S / fmaxf(sqrtf(ss), 1e-12f);
        uint8_t* dst = isW ? g_W8 : g_F8;
        uint32_t* o32 = (uint32_t*)(dst + (size_t)row * D_DIM);
        o32[lane +  0] = pack_e4m3x4(v[0].x * sc, v[0].y * sc, v[0].z * sc, v[0].w * sc);
        o32[lane + 32] = pack_e4m3x4(v[1].x * sc, v[1].y * sc, v[1].z * sc, v[1].w * sc);
        o32[lane + 64] = pack_e4m3x4(v[2].x * sc, v[2].y * sc, v[2].z * sc, v[2].w * sc);
        o32[lane + 96] = pack_e4m3x4(v[3].x * sc, v[3].y * sc, v[3].z * sc, v[3].w * sc);
    } else {
        int row = (bid - PREP_W_BLOCKS - PREP_F_BLOCKS) * 8 + warp;
        int cls = Y[row];
        const float4* fp = (const float4*)(F + (size_t)row * D_DIM);
        const float4* wp = (const float4*)(W + (size_t)cls * D_DIM);
        float dot = 0.0f, ff = 0.0f, ww = 0.0f;
#pragma unroll
        for (int i = 0; i < 4; i++) {
            float4 a = fp[lane + 32 * i];
            float4 b = wp[lane + 32 * i];
            dot = fmaf(a.x, b.x, fmaf(a.y, b.y, fmaf(a.z, b.z, fmaf(a.w, b.w, dot))));
            ff  = fmaf(a.x, a.x, fmaf(a.y, a.y, fmaf(a.z, a.z, fmaf(a.w, a.w, ff))));
            ww  = fmaf(b.x, b.x, fmaf(b.y, b.y, fmaf(b.z, b.z, fmaf(b.w, b.w, ww))));
        }
#pragma unroll
        for (int o = 16; o; o >>= 1) {
            dot += __shfl_xor_sync(0xffffffffu, dot, o);
            ff  += __shfl_xor_sync(0xffffffffu, ff,  o);
            ww  += __shfl_xor_sync(0xffffffffu, ww,  o);
        }
        if (lane == 0)
            g_tgt[row] = dot / (fmaxf(sqrtf(ff), 1e-12f) * fmaxf(sqrtf(ww), 1e-12f));
    }
}

// ---------------------------------------------------------------------------
// Persistent fp8 mma GEMM: 296 CTAs, each owns tiles bid + t*296.
// R10's proven 2-stage cp.async ring runs CONTINUOUSLY across tiles:
// prefetch of global chunk g+2 (possibly next tile's chunk) keeps the ring
// full through tile boundaries; per-tile epilogue overlaps in-flight DMA.
// stage layout (32 KB): A 128x128B at +0 (swizzle j ^ (row&7)), B at +16384.
__global__ void __launch_bounds__(256, 2)
gemm_exp_mma_kernel() {
    extern __shared__ __align__(16) char smb[];   // 2 * 32KB
    const uint32_t smbase = smem_u32(smb);
    const int tid  = threadIdx.x;
    const int lane = tid & 31;
    const int warp = tid >> 5;
    const int wm = warp >> 2;          // 0..1
    const int wn = warp & 3;           // 0..3
    const int bid = blockIdx.x;

    // ---- cp.async setup: per thread 4x16B of A + 4x16B of B per chunk ----
    const int jj = tid & 7;            // 16B column
    const int r0 = tid >> 3;           // base row 0..31 (rows r0 + 32i)
    const uint32_t dA = (uint32_t)(r0 * 128 + ((jj ^ (r0 & 7)) << 4));
    const uint32_t dB = dA + B_REGION;
    const uint8_t* fBase = g_F8 + (size_t)r0 * D_DIM + jj * 16;
    const uint8_t* wBase = g_W8 + (size_t)r0 * D_DIM + jj * 16;

    const int myTiles = (NTILES - 1 - bid) / GRIDP + 1;
    const int total = myTiles * 4;     // global chunk count for this CTA

    // ---- ldmatrix lane addressing ----
    const int l15 = lane & 15, xorl = lane & 7, hi = lane >> 4;
    uint32_t xk[4];
#pragma unroll
    for (int ks = 0; ks < 4; ks++)
        xk[ks] = (uint32_t)((((ks << 1) | hi) ^ xorl) << 4);
    const uint32_t aBase = smbase + ((wm * 64 + l15) << 7);
    const uint32_t bBase = smbase + B_REGION + ((wn * 32 + l15) << 7);

    // prefetch helper: global chunk g2 -> stage g2&1
    auto prefetch = [&](int g2) {
        const int ti = g2 >> 2, c2 = g2 & 3;
        const int tile = bid + ti * GRIDP;
        const uint8_t* pa = fBase + (size_t)((tile >> 8) * BM) * D_DIM + c2 * 128;
        const uint8_t* pb = wBase + (size_t)((tile & 255) * BN) * D_DIM + c2 * 128;
        const uint32_t st = smbase + (uint32_t)(g2 & 1) * BUF_BYTES;
#pragma unroll
        for (int i = 0; i < 4; i++) {
            cpasync16(st + dA + i * 4096, pa + i * 16384);
            cpasync16(st + dB + i * 4096, pb + i * 16384);
        }
        CP_COMMIT;
    };

    prefetch(0);
    prefetch(1);

    int g = 0;
#pragma unroll 1
    for (int t = 0; t < myTiles; t++) {
        const int tile = bid + t * GRIDP;
        const int tm = tile >> 8;

        float acc[4][4][4];
#pragma unroll
        for (int a = 0; a < 4; a++)
#pragma unroll
            for (int b = 0; b < 4; b++)
#pragma unroll
                for (int c = 0; c < 4; c++) acc[a][b][c] = 0.0f;

#pragma unroll
        for (int c = 0; c < 4; c++, g++) {
            if (g + 1 < total) { CP_WAIT1; } else { CP_WAIT0; }
            __syncthreads();
            const uint32_t bo = (uint32_t)(g & 1) * BUF_BYTES;
#pragma unroll
            for (int ks = 0; ks < 4; ks++) {
                uint4 afr[4], b0, b1;
#pragma unroll
                for (int mt = 0; mt < 4; mt++)
                    ldsm4(afr[mt], aBase + bo + (mt << 11) + xk[ks]);
                ldsm4(b0, bBase + bo + xk[ks]);
                ldsm4(b1, bBase + bo + (1 << 11) + xk[ks]);
#pragma unroll
                for (int mt = 0; mt < 4; mt++) {
                    mma_f8(acc[mt][0], afr[mt], b0.x, b0.z);
                    mma_f8(acc[mt][1], afr[mt], b0.y, b0.w);
                    mma_f8(acc[mt][2], afr[mt], b1.x, b1.z);
                    mma_f8(acc[mt][3], afr[mt], b1.y, b1.w);
                }
            }
            if (g + 2 < total) {
                __syncthreads();   // all warps done reading stage g&1
                prefetch(g + 2);   // refill it (next tile's chunks near boundary)
            }
        }

        // ---- per-tile epilogue: exp + row reduce + atomicAdd ----
        float s[4][2];
#pragma unroll
        for (int mt = 0; mt < 4; mt++) {
            float s0 = 0.0f, s1 = 0.0f;
#pragma unroll
            for (int nt = 0; nt < 4; nt++) {
                s0 += __expf(acc[mt][nt][0]) + __expf(acc[mt][nt][1]);
                s1 += __expf(acc[mt][nt][2]) + __expf(acc[mt][nt][3]);
            }
            s[mt][0] = s0; s[mt][1] = s1;
        }
#pragma unroll
        for (int o = 1; o < 4; o <<= 1)
#pragma unroll
            for (int mt = 0; mt < 4; mt++) {
                s[mt][0] += __shfl_xor_sync(0xffffffffu, s[mt][0], o);
                s[mt][1] += __shfl_xor_sync(0xffffffffu, s[mt][1], o);
            }
        if ((lane & 3) == 0) {
            int gg = lane >> 2;
            int base = tm * BM + wm * 64 + gg;
#pragma unroll
            for (int mt = 0; mt < 4; mt++) {
                atomicAdd(&g_rowsum[base + mt * 16],     s[mt][0]);
                atomicAdd(&g_rowsum[base + mt * 16 + 8], s[mt][1]);
            }
        }
    }
}

// ---------------------------------------------------------------------------
__global__ void loss_kernel(float* __restrict__ out) {
    __shared__ double sh[1024];
    double a = 0.0;
    for (int b = threadIdx.x; b < B_ROWS; b += blockDim.x) {
        float t = fminf(fmaxf(g_tgt[b], -1.0f + EPS_CLIP), 1.0f - EPS_CLIP);
        float num = S_SCALE * cosf(acosf(t) + MARGIN);
        float excl = g_rowsum[b] - __expf(S_SCALE * t);
        double denom = (double)__expf(num) + (double)excl;
        a += (double)num - log(denom);
    }
    sh[threadIdx.x] = a;
    __syncthreads();
    for (int s = 512; s > 0; s >>= 1) {
        if (threadIdx.x < s) sh[threadIdx.x] += sh[threadIdx.x + s];
        __syncthreads();
    }
    if (threadIdx.x == 0) out[0] = (float)(-sh[0] / (double)B_ROWS);
}

// ---------------------------------------------------------------------------
extern "C" void kernel_launch(void* const* d_in, const int* in_sizes, int n_in,
                              void* d_out, int out_size) {
    const float* F = (const float*)d_in[0];
    const int*   Y = (const int*)d_in[1];
    const float* W = (const float*)d_in[2];
    float* out = (float*)d_out;

    cudaFuncSetAttribute(gemm_exp_mma_kernel,
                         cudaFuncAttributeMaxDynamicSharedMemorySize, SMEM_TOTAL);

    prep_kernel<<<PREP_BLOCKS, 256>>>(F, Y, W);

    gemm_exp_mma_kernel<<<GRIDP, 256, SMEM_TOTAL>>>();

    loss_kernel<<<1, 1024>>>(out);
}

// round 15
// speedup vs baseline: 1.0837x; 1.0366x over previous
#include <cuda_runtime.h>
#include <math.h>
#include <stdint.h>

#define B_ROWS 2048
#define D_DIM  512
#define C_CLS  32768
#define S_SCALE 64.0f
#define SQRT_S 8.0f
#define MARGIN  0.5f
#define EPS_CLIP 1e-7f

#define BM 128
#define BN 128
#define NCH 4                    // 512 / 128 bytes per chunk
#define BUF_BYTES 32768          // A 16KB + B 16KB per stage
#define B_REGION  16384

// prep grid: 2 rows per warp for W/F, warp-per-row for tgt
#define PREP_W_BLOCKS  (C_CLS / 16)            // 2048
#define PREP_F_BLOCKS  (B_ROWS / 16)           // 128
#define PREP_T_BLOCKS  (B_ROWS / 8)            // 256
#define PREP_BLOCKS    (PREP_W_BLOCKS + PREP_F_BLOCKS + PREP_T_BLOCKS)

// ---------------------------------------------------------------------------
__device__ float  g_rowsum[B_ROWS];
__device__ float  g_tgt[B_ROWS];
__device__ __align__(16) uint8_t g_F8[B_ROWS * D_DIM];   // e4m3(8 * f_hat)
__device__ __align__(16) uint8_t g_W8[C_CLS * D_DIM];    // e4m3(8 * w_hat)

// ---------------------------------------------------------------------------
__device__ __forceinline__ uint32_t smem_u32(const void* p) {
    uint32_t a;
    asm("{ .reg .u64 t; cvta.to.shared.u64 t, %1; cvt.u32.u64 %0, t; }" : "=r"(a) : "l"(p));
    return a;
}

__device__ __forceinline__ void mma_f8(float* c, const uint4& a,
                                       uint32_t b0, uint32_t b1) {
    asm volatile(
        "mma.sync.aligned.m16n8k32.row.col.f32.e4m3.e4m3.f32 "
        "{%0,%1,%2,%3}, {%4,%5,%6,%7}, {%8,%9}, {%0,%1,%2,%3};"
        : "+f"(c[0]), "+f"(c[1]), "+f"(c[2]), "+f"(c[3])
        : "r"(a.x), "r"(a.y), "r"(a.z), "r"(a.w), "r"(b0), "r"(b1));
}

__device__ __forceinline__ void ldsm4(uint4& d, uint32_t a) {
    asm volatile("ldmatrix.sync.aligned.m8n8.x4.shared.b16 {%0,%1,%2,%3}, [%4];"
                 : "=r"(d.x), "=r"(d.y), "=r"(d.z), "=r"(d.w) : "r"(a));
}

__device__ __forceinline__ void cpasync16cg(uint32_t dst, const void* src) {
    asm volatile("cp.async.cg.shared.global [%0], [%1], 16;" :: "r"(dst), "l"(src));
}
__device__ __forceinline__ void cpasync16ca(uint32_t dst, const void* src) {
    asm volatile("cp.async.ca.shared.global [%0], [%1], 16;" :: "r"(dst), "l"(src));
}
#define CP_COMMIT asm volatile("cp.async.commit_group;" ::: "memory")
#define CP_WAIT1  asm volatile("cp.async.wait_group 1;" ::: "memory")
#define CP_WAIT0  asm volatile("cp.async.wait_group 0;" ::: "memory")

__device__ __forceinline__ uint32_t pack_e4m3x2(float lo, float hi) {
    uint16_t r;
    asm("cvt.rn.satfinite.e4m3x2.f32 %0, %1, %2;" : "=h"(r) : "f"(hi), "f"(lo));
    return (uint32_t)r;
}
__device__ __forceinline__ uint32_t pack_e4m3x4(float a, float b, float c, float d) {
    return pack_e4m3x2(a, b) | (pack_e4m3x2(c, d) << 16);
}

// ---------------------------------------------------------------------------
// Fused prep, MLP=8 (2 rows per warp, all loads front-batched):
//   blocks [0, 2048)    : W rows -> g_W8 = e4m3(8 * w_hat)
//   blocks [2048, 2176) : F rows -> g_F8 = e4m3(8 * f_hat), zero g_rowsum
//   blocks [2176, 2432) : target cosine (exact fp32, self-contained)
__global__ void prep_kernel(const float* __restrict__ F,
                            const int* __restrict__ Y,
                            const float* __restrict__ W) {
    const int bid  = blockIdx.x;
    const int warp = threadIdx.x >> 5;
    const int lane = threadIdx.x & 31;

    if (bid < PREP_W_BLOCKS + PREP_F_BLOCKS) {
        const bool isW = bid < PREP_W_BLOCKS;
        int row0 = isW ? (bid * 16 + warp * 2)
                       : ((bid - PREP_W_BLOCKS) * 16 + warp * 2);
        const float* src = isW ? W : F;
        if (!isW && lane < 2) g_rowsum[row0 + lane] = 0.0f;
        const float4* p0 = (const float4*)(src + (size_t)row0 * D_DIM);
        const float4* p1 = (const float4*)(src + (size_t)(row0 + 1) * D_DIM);
        float4 v0[4], v1[4];
#pragma unroll
        for (int i = 0; i < 4; i++) { v0[i] = p0[lane + 32 * i]; v1[i] = p1[lane + 32 * i]; }
        float ss0 = 0.0f, ss1 = 0.0f;
#pragma unroll
        for (int i = 0; i < 4; i++) {
            ss0 = fmaf(v0[i].x, v0[i].x, fmaf(v0[i].y, v0[i].y, fmaf(v0[i].z, v0[i].z, fmaf(v0[i].w, v0[i].w, ss0))));
            ss1 = fmaf(v1[i].x, v1[i].x, fmaf(v1[i].y, v1[i].y, fmaf(v1[i].z, v1[i].z, fmaf(v1[i].w, v1[i].w, ss1))));
        }
#pragma unroll
        for (int o = 16; o; o >>= 1) {
            ss0 += __shfl_xor_sync(0xffffffffu, ss0, o);
            ss1 += __shfl_xor_sync(0xffffffffu, ss1, o);
        }
        float sc0 = SQRT_S / fmaxf(sqrtf(ss0), 1e-12f);
        float sc1 = SQRT_S / fmaxf(sqrtf(ss1), 1e-12f);
        uint8_t* dst = isW ? g_W8 : g_F8;
        uint32_t* o0 = (uint32_t*)(dst + (size_t)row0 * D_DIM);
        uint32_t* o1 = (uint32_t*)(dst + (size_t)(row0 + 1) * D_DIM);
#pragma unroll
        for (int i = 0; i < 4; i++) {
            o0[lane + 32 * i] = pack_e4m3x4(v0[i].x * sc0, v0[i].y * sc0, v0[i].z * sc0, v0[i].w * sc0);
            o1[lane + 32 * i] = pack_e4m3x4(v1[i].x * sc1, v1[i].y * sc1, v1[i].z * sc1, v1[i].w * sc1);
        }
    } else {
        int row = (bid - PREP_W_BLOCKS - PREP_F_BLOCKS) * 8 + warp;
        int cls = Y[row];
        const float4* fp = (const float4*)(F + (size_t)row * D_DIM);
        const float4* wp = (const float4*)(W + (size_t)cls * D_DIM);
        float dot = 0.0f, ff = 0.0f, ww = 0.0f;
#pragma unroll
        for (int i = 0; i < 4; i++) {
            float4 a = fp[lane + 32 * i];
            float4 b = wp[lane + 32 * i];
            dot = fmaf(a.x, b.x, fmaf(a.y, b.y, fmaf(a.z, b.z, fmaf(a.w, b.w, dot))));
            ff  = fmaf(a.x, a.x, fmaf(a.y, a.y, fmaf(a.z, a.z, fmaf(a.w, a.w, ff))));
            ww  = fmaf(b.x, b.x, fmaf(b.y, b.y, fmaf(b.z, b.z, fmaf(b.w, b.w, ww))));
        }
#pragma unroll
        for (int o = 16; o; o >>= 1) {
            dot += __shfl_xor_sync(0xffffffffu, dot, o);
            ff  += __shfl_xor_sync(0xffffffffu, ff,  o);
            ww  += __shfl_xor_sync(0xffffffffu, ww,  o);
        }
        if (lane == 0)
            g_tgt[row] = dot / (fmaxf(sqrtf(ff), 1e-12f) * fmaxf(sqrtf(ww), 1e-12f));
    }
}

// ---------------------------------------------------------------------------
// fp8 mma GEMM (R10 structure verbatim): cp.async staging + ldmatrix loads.
// A uses cp.async.ca (L1-resident across CTAs sharing tm); B uses .cg.
// smem layout per buffer (32 KB): A 128x128B at +0, B at +16384.
// swizzle: 16B column j stored at j ^ (row & 7).
__global__ void __launch_bounds__(256, 2)
gemm_exp_mma_kernel() {
    extern __shared__ __align__(16) char smb[];   // 2 * 32KB
    const uint32_t smbase = smem_u32(smb);
    const int tid  = threadIdx.x;
    const int lane = tid & 31;
    const int warp = tid >> 5;
    const int wm = warp >> 2;          // 0..1
    const int wn = warp & 3;           // 0..3
    const int tm = blockIdx.y;
    const int tn = blockIdx.x;

    // ---- cp.async setup: per thread 4x16B of A + 4x16B of B per chunk ----
    const int jj = tid & 7;            // 16B column
    const int r0 = tid >> 3;           // base row 0..31 (rows r0 + 32i)
    const uint32_t dA = (uint32_t)(r0 * 128 + ((jj ^ (r0 & 7)) << 4));
    const uint32_t dB = dA + B_REGION;
    const uint8_t* sA = g_F8 + (size_t)(tm * BM + r0) * D_DIM + jj * 16;
    const uint8_t* sB = g_W8 + (size_t)(tn * BN + r0) * D_DIM + jj * 16;

    // ---- ldmatrix lane addressing ----
    const int l15 = lane & 15, xorl = lane & 7, hi = lane >> 4;
    uint32_t xk[4];
#pragma unroll
    for (int ks = 0; ks < 4; ks++)
        xk[ks] = (uint32_t)((((ks << 1) | hi) ^ xorl) << 4);
    const uint32_t aBase = smbase + ((wm * 64 + l15) << 7);
    const uint32_t bBase = smbase + B_REGION + ((wn * 32 + l15) << 7);

    float acc[4][4][4];
#pragma unroll
    for (int a = 0; a < 4; a++)
#pragma unroll
        for (int b = 0; b < 4; b++)
#pragma unroll
            for (int c = 0; c < 4; c++) acc[a][b][c] = 0.0f;

    // ---- prologue: prefetch chunks 0 and 1 ----
#pragma unroll
    for (int i = 0; i < 4; i++) {
        cpasync16ca(smbase + dA + i * 4096, sA + i * 16384);
        cpasync16cg(smbase + dB + i * 4096, sB + i * 16384);
    }
    CP_COMMIT;
#pragma unroll
    for (int i = 0; i < 4; i++) {
        cpasync16ca(smbase + BUF_BYTES + dA + i * 4096, sA + 128 + i * 16384);
        cpasync16cg(smbase + BUF_BYTES + dB + i * 4096, sB + 128 + i * 16384);
    }
    CP_COMMIT;

#pragma unroll
    for (int c = 0; c < NCH; c++) {
        if (c < NCH - 1) { CP_WAIT1; } else { CP_WAIT0; }
        __syncthreads();
        const uint32_t bo = (uint32_t)(c & 1) * BUF_BYTES;
#pragma unroll
        for (int ks = 0; ks < 4; ks++) {
            uint4 afr[4], b0, b1;
#pragma unroll
            for (int mt = 0; mt < 4; mt++)
                ldsm4(afr[mt], aBase + bo + (mt << 11) + xk[ks]);
            ldsm4(b0, bBase + bo + xk[ks]);
            ldsm4(b1, bBase + bo + (1 << 11) + xk[ks]);
#pragma unroll
            for (int mt = 0; mt < 4; mt++) {
                mma_f8(acc[mt][0], afr[mt], b0.x, b0.z);
                mma_f8(acc[mt][1], afr[mt], b0.y, b0.w);
                mma_f8(acc[mt][2], afr[mt], b1.x, b1.z);
                mma_f8(acc[mt][3], afr[mt], b1.y, b1.w);
            }
        }
        if (c + 2 < NCH) {
            __syncthreads();   // everyone done reading this buffer
            const uint8_t* pa = sA + (c + 2) * 128;
            const uint8_t* pb = sB + (c + 2) * 128;
#pragma unroll
            for (int i = 0; i < 4; i++) {
                cpasync16ca(smbase + bo + dA + i * 4096, pa + i * 16384);
                cpasync16cg(smbase + bo + dB + i * 4096, pb + i * 16384);
            }
            CP_COMMIT;
        }
    }

    // ---- epilogue: exp + row reduce + atomicAdd ----
    float s[4][2];
#pragma unroll
    for (int mt = 0; mt < 4; mt++) {
        float s0 = 0.0f, s1 = 0.0f;
#pragma unroll
        for (int nt = 0; nt < 4; nt++) {
            s0 += __expf(acc[mt][nt][0]) + __expf(acc[mt][nt][1]);
            s1 += __expf(acc[mt][nt][2]) + __expf(acc[mt][nt][3]);
        }
        s[mt][0] = s0; s[mt][1] = s1;
    }
#pragma unroll
    for (int o = 1; o < 4; o <<= 1)
#pragma unroll
        for (int mt = 0; mt < 4; mt++) {
            s[mt][0] += __shfl_xor_sync(0xffffffffu, s[mt][0], o);
            s[mt][1] += __shfl_xor_sync(0xffffffffu, s[mt][1], o);
        }
    if ((lane & 3) == 0) {
        int g = lane >> 2;
        int base = tm * BM + wm * 64 + g;
#pragma unroll
        for (int mt = 0; mt < 4; mt++) {
            atomicAdd(&g_rowsum[base + mt * 16],     s[mt][0]);
            atomicAdd(&g_rowsum[base + mt * 16 + 8], s[mt][1]);
        }
    }
}

// ---------------------------------------------------------------------------
__global__ void loss_kernel(float* __restrict__ out) {
    __shared__ double sh[1024];
    double a = 0.0;
    for (int b = threadIdx.x; b < B_ROWS; b += blockDim.x) {
        float t = fminf(fmaxf(g_tgt[b], -1.0f + EPS_CLIP), 1.0f - EPS_CLIP);
        float num = S_SCALE * cosf(acosf(t) + MARGIN);
        float excl = g_rowsum[b] - __expf(S_SCALE * t);
        double denom = (double)__expf(num) + (double)excl;
        a += (double)num - log(denom);
    }
    sh[threadIdx.x] = a;
    __syncthreads();
    for (int s = 512; s > 0; s >>= 1) {
        if (threadIdx.x < s) sh[threadIdx.x] += sh[threadIdx.x + s];
        __syncthreads();
    }
    if (threadIdx.x == 0) out[0] = (float)(-sh[0] / (double)B_ROWS);
}

// ---------------------------------------------------------------------------
extern "C" void kernel_launch(void* const* d_in, const int* in_sizes, int n_in,
                              void* d_out, int out_size) {
    const float* F = (const float*)d_in[0];
    const int*   Y = (const int*)d_in[1];
    const float* W = (const float*)d_in[2];
    float* out = (float*)d_out;

    cudaFuncSetAttribute(gemm_exp_mma_kernel,
                         cudaFuncAttributeMaxDynamicSharedMemorySize, 2 * BUF_BYTES);

    prep_kernel<<<PREP_BLOCKS, 256>>>(F, Y, W);

    dim3 grid(C_CLS / BN, B_ROWS / BM);   // (256, 16)
    gemm_exp_mma_kernel<<<grid, 256, 2 * BUF_BYTES>>>();

    loss_kernel<<<1, 1024>>>(out);
}

// round 16
// speedup vs baseline: 1.1174x; 1.0310x over previous
#include <cuda_runtime.h>
#include <math.h>
#include <stdint.h>

#define B_ROWS 2048
#define D_DIM  512
#define C_CLS  32768
#define S_SCALE 64.0f
#define SQRT_S 8.0f
#define MARGIN  0.5f
#define EPS_CLIP 1e-7f

#define BM 128
#define BN 128
#define NCH 4                    // 4 k-chunks of 128 B
#define CHUNK_BYTES 16384        // one operand chunk: 128 rows x 128 B
#define TILE_BYTES  65536        // 4 chunks
#define BUF_BYTES 32768          // A 16KB + B 16KB per stage
#define B_REGION  16384
#define MB_OFF    65536          // mbarriers after the 2 stages
#define SMEM_TOTAL (2 * BUF_BYTES + 128)

// prep grid split (8 warps = 8 rows per block)
#define PREP_W_BLOCKS  (C_CLS / 8)             // 4096
#define PREP_F_BLOCKS  (B_ROWS / 8)            // 256
#define PREP_T_BLOCKS  (B_ROWS / 8)            // 256
#define PREP_BLOCKS    (PREP_W_BLOCKS + PREP_F_BLOCKS + PREP_T_BLOCKS)

// ---------------------------------------------------------------------------
// Blocked + pre-swizzled e4m3 scratch:
//   g_F8: [16 tiles][4 chunks][128 rows][128 B], 16B col j stored at j^(row&7)
//   g_W8: [256 tiles][4 chunks][128 rows][128 B], same swizzle
__device__ float  g_rowsum[B_ROWS];
__device__ float  g_tgt[B_ROWS];
__device__ __align__(128) uint8_t g_F8[B_ROWS * D_DIM];
__device__ __align__(128) uint8_t g_W8[C_CLS * D_DIM];

// ---------------------------------------------------------------------------
__device__ __forceinline__ uint32_t smem_u32(const void* p) {
    uint32_t a;
    asm("{ .reg .u64 t; cvta.to.shared.u64 t, %1; cvt.u32.u64 %0, t; }" : "=r"(a) : "l"(p));
    return a;
}

__device__ __forceinline__ void mma_f8(float* c, const uint4& a,
                                       uint32_t b0, uint32_t b1) {
    asm volatile(
        "mma.sync.aligned.m16n8k32.row.col.f32.e4m3.e4m3.f32 "
        "{%0,%1,%2,%3}, {%4,%5,%6,%7}, {%8,%9}, {%0,%1,%2,%3};"
        : "+f"(c[0]), "+f"(c[1]), "+f"(c[2]), "+f"(c[3])
        : "r"(a.x), "r"(a.y), "r"(a.z), "r"(a.w), "r"(b0), "r"(b1));
}

__device__ __forceinline__ void ldsm4(uint4& d, uint32_t a) {
    asm volatile("ldmatrix.sync.aligned.m8n8.x4.shared.b16 {%0,%1,%2,%3}, [%4];"
                 : "=r"(d.x), "=r"(d.y), "=r"(d.z), "=r"(d.w) : "r"(a));
}

// one-instruction 16KB DMA: global -> shared, completion via mbarrier tx-count
__device__ __forceinline__ void bulkcp(uint32_t dst, const void* src,
                                       uint32_t bytes, uint32_t mbar) {
    asm volatile(
        "cp.async.bulk.shared::cluster.global.mbarrier::complete_tx::bytes "
        "[%0], [%1], %2, [%3];"
        :: "r"(dst), "l"(src), "r"(bytes), "r"(mbar) : "memory");
}
#define MBAR_INIT(bar, cnt) \
    asm volatile("mbarrier.init.shared.b64 [%0], %1;" :: "r"(bar), "r"(cnt) : "memory")
#define MBAR_EXPECT_TX(bar, bytes) \
    asm volatile("mbarrier.arrive.expect_tx.shared.b64 _, [%0], %1;" :: "r"(bar), "r"(bytes) : "memory")
__device__ __forceinline__ void mbar_wait(uint32_t bar, uint32_t parity) {
    asm volatile(
        "{\n\t.reg .pred P;\n\t"
        "W%=:\n\t"
        "mbarrier.try_wait.parity.acquire.cta.shared::cta.b64 P, [%0], %1, 0x989680;\n\t"
        "@P bra D%=;\n\t"
        "bra W%=;\n\t"
        "D%=:\n\t}"
        :: "r"(bar), "r"(parity) : "memory");
}

__device__ __forceinline__ uint32_t pack_e4m3x2(float lo, float hi) {
    uint16_t r;
    asm("cvt.rn.satfinite.e4m3x2.f32 %0, %1, %2;" : "=h"(r) : "f"(hi), "f"(lo));
    return (uint32_t)r;
}
__device__ __forceinline__ uint32_t pack_e4m3x4(float a, float b, float c, float d) {
    return pack_e4m3x2(a, b) | (pack_e4m3x2(c, d) << 16);
}

// ---------------------------------------------------------------------------
// Fused prep -> blocked + pre-swizzled layout.
//   word i of 4 per lane == k-chunk i;  within-chunk 16B group = lane>>2,
//   stored at group ((lane>>2) ^ (row&7)), word (lane&3).
__global__ void prep_kernel(const float* __restrict__ F,
                            const int* __restrict__ Y,
                            const float* __restrict__ W) {
    const int bid  = blockIdx.x;
    const int warp = threadIdx.x >> 5;
    const int lane = threadIdx.x & 31;

    if (bid < PREP_W_BLOCKS + PREP_F_BLOCKS) {
        const bool isW = bid < PREP_W_BLOCKS;
        int row = isW ? (bid * 8 + warp) : ((bid - PREP_W_BLOCKS) * 8 + warp);
        const float* src = isW ? W : F;
        if (!isW && lane == 0) g_rowsum[row] = 0.0f;
        const float4* p = (const float4*)(src + (size_t)row * D_DIM);
        float4 v[4]; float ss = 0.0f;
#pragma unroll
        for (int i = 0; i < 4; i++) {
            v[i] = p[lane + 32 * i];
            ss = fmaf(v[i].x, v[i].x, fmaf(v[i].y, v[i].y, fmaf(v[i].z, v[i].z, fmaf(v[i].w, v[i].w, ss))));
        }
#pragma unroll
        for (int o = 16; o; o >>= 1) ss += __shfl_xor_sync(0xffffffffu, ss, o);
        float sc = SQRT_S / fmaxf(sqrtf(ss), 1e-12f);
        uint32_t* o32 = (uint32_t*)(isW ? g_W8 : g_F8);
        const int tile = row >> 7, rr = row & 127;
        const size_t base = (size_t)tile * 16384 + (size_t)rr * 32;   // words
        const int sw = ((((lane >> 2) ^ (rr & 7)) << 2) | (lane & 3));
#pragma unroll
        for (int i = 0; i < 4; i++)
            o32[base + (size_t)i * 4096 + sw] =
                pack_e4m3x4(v[i].x * sc, v[i].y * sc, v[i].z * sc, v[i].w * sc);
    } else {
        int row = (bid - PREP_W_BLOCKS - PREP_F_BLOCKS) * 8 + warp;
        int cls = Y[row];
        const float4* fp = (const float4*)(F + (size_t)row * D_DIM);
        const float4* wp = (const float4*)(W + (size_t)cls * D_DIM);
        float dot = 0.0f, ff = 0.0f, ww = 0.0f;
#pragma unroll
        for (int i = 0; i < 4; i++) {
            float4 a = fp[lane + 32 * i];
            float4 b = wp[lane + 32 * i];
            dot = fmaf(a.x, b.x, fmaf(a.y, b.y, fmaf(a.z, b.z, fmaf(a.w, b.w, dot))));
            ff  = fmaf(a.x, a.x, fmaf(a.y, a.y, fmaf(a.z, a.z, fmaf(a.w, a.w, ff))));
            ww  = fmaf(b.x, b.x, fmaf(b.y, b.y, fmaf(b.z, b.z, fmaf(b.w, b.w, ww))));
        }
#pragma unroll
        for (int o = 16; o; o >>= 1) {
            dot += __shfl_xor_sync(0xffffffffu, dot, o);
            ff  += __shfl_xor_sync(0xffffffffu, ff,  o);
            ww  += __shfl_xor_sync(0xffffffffu, ww,  o);
        }
        if (lane == 0)
            g_tgt[row] = dot / (fmaxf(sqrtf(ff), 1e-12f) * fmaxf(sqrtf(ww), 1e-12f));
    }
}

// ---------------------------------------------------------------------------
// fp8 mma GEMM: R10 mainloop, but staging via cp.async.bulk (2 DMA/chunk)
// + mbarrier completion instead of 2048 LDGSTS per chunk.
// smem stage (32 KB): A 128x128B at +0 (pre-swizzled in global), B at +16384.
__global__ void __launch_bounds__(256, 2)
gemm_exp_mma_kernel() {
    extern __shared__ __align__(128) char smb[];   // 2*32KB + mbarriers
    const uint32_t smbase = smem_u32(smb);
    const int tid  = threadIdx.x;
    const int lane = tid & 31;
    const int warp = tid >> 5;
    const int wm = warp >> 2;          // 0..1
    const int wn = warp & 3;           // 0..3
    const int tm = blockIdx.y;
    const int tn = blockIdx.x;

    const uint32_t mb = smbase + MB_OFF;   // two 8B mbarriers
    if (tid == 0) { MBAR_INIT(mb, 1); MBAR_INIT(mb + 8, 1); }
    __syncthreads();

    const uint8_t* srcA = g_F8 + (size_t)tm * TILE_BYTES;
    const uint8_t* srcB = g_W8 + (size_t)tn * TILE_BYTES;

    // ---- ldmatrix lane addressing (same as R10) ----
    const int l15 = lane & 15, xorl = lane & 7, hi = lane >> 4;
    uint32_t xk[4];
#pragma unroll
    for (int ks = 0; ks < 4; ks++)
        xk[ks] = (uint32_t)((((ks << 1) | hi) ^ xorl) << 4);
    const uint32_t aBase = smbase + ((wm * 64 + l15) << 7);
    const uint32_t bBase = smbase + B_REGION + ((wn * 32 + l15) << 7);

    float acc[4][4][4];
#pragma unroll
    for (int a = 0; a < 4; a++)
#pragma unroll
        for (int b = 0; b < 4; b++)
#pragma unroll
            for (int c = 0; c < 4; c++) acc[a][b][c] = 0.0f;

    // ---- prologue: DMA chunks 0 and 1 into stages 0 and 1 ----
    if (tid == 0) {
#pragma unroll
        for (int s = 0; s < 2; s++) {
            const uint32_t bar = mb + s * 8;
            MBAR_EXPECT_TX(bar, BUF_BYTES);
            bulkcp(smbase + s * BUF_BYTES,            srcA + s * CHUNK_BYTES, CHUNK_BYTES, bar);
            bulkcp(smbase + s * BUF_BYTES + B_REGION, srcB + s * CHUNK_BYTES, CHUNK_BYTES, bar);
        }
    }

#pragma unroll
    for (int c = 0; c < NCH; c++) {
        mbar_wait(mb + (c & 1) * 8, (c >> 1) & 1);
        const uint32_t bo = (uint32_t)(c & 1) * BUF_BYTES;
#pragma unroll
        for (int ks = 0; ks < 4; ks++) {
            uint4 afr[4], b0, b1;
#pragma unroll
            for (int mt = 0; mt < 4; mt++)
                ldsm4(afr[mt], aBase + bo + (mt << 11) + xk[ks]);
            ldsm4(b0, bBase + bo + xk[ks]);
            ldsm4(b1, bBase + bo + (1 << 11) + xk[ks]);
#pragma unroll
            for (int mt = 0; mt < 4; mt++) {
                mma_f8(acc[mt][0], afr[mt], b0.x, b0.z);
                mma_f8(acc[mt][1], afr[mt], b0.y, b0.w);
                mma_f8(acc[mt][2], afr[mt], b1.x, b1.z);
                mma_f8(acc[mt][3], afr[mt], b1.y, b1.w);
            }
        }
        if (c + 2 < NCH) {
            __syncthreads();   // all warps done reading stage c&1
            if (tid == 0) {
                const uint32_t bar = mb + (c & 1) * 8;
                MBAR_EXPECT_TX(bar, BUF_BYTES);
                bulkcp(bo + smbase,            srcA + (c + 2) * CHUNK_BYTES, CHUNK_BYTES, bar);
                bulkcp(bo + smbase + B_REGION, srcB + (c + 2) * CHUNK_BYTES, CHUNK_BYTES, bar);
            }
        }
    }

    // ---- epilogue: exp + row reduce + atomicAdd ----
    float s[4][2];
#pragma unroll
    for (int mt = 0; mt < 4; mt++) {
        float s0 = 0.0f, s1 = 0.0f;
#pragma unroll
        for (int nt = 0; nt < 4; nt++) {
            s0 += __expf(acc[mt][nt][0]) + __expf(acc[mt][nt][1]);
            s1 += __expf(acc[mt][nt][2]) + __expf(acc[mt][nt][3]);
        }
        s[mt][0] = s0; s[mt][1] = s1;
    }
#pragma unroll
    for (int o = 1; o < 4; o <<= 1)
#pragma unroll
        for (int mt = 0; mt < 4; mt++) {
            s[mt][0] += __shfl_xor_sync(0xffffffffu, s[mt][0], o);
            s[mt][1] += __shfl_xor_sync(0xffffffffu, s[mt][1], o);
        }
    if ((lane & 3) == 0) {
        int g = lane >> 2;
        int base = tm * BM + wm * 64 + g;
#pragma unroll
        for (int mt = 0; mt < 4; mt++) {
            atomicAdd(&g_rowsum[base + mt * 16],     s[mt][0]);
            atomicAdd(&g_rowsum[base + mt * 16 + 8], s[mt][1]);
        }
    }
}

// ---------------------------------------------------------------------------
__global__ void loss_kernel(float* __restrict__ out) {
    __shared__ double sh[1024];
    double a = 0.0;
    for (int b = threadIdx.x; b < B_ROWS; b += blockDim.x) {
        float t = fminf(fmaxf(g_tgt[b], -1.0f + EPS_CLIP), 1.0f - EPS_CLIP);
        float num = S_SCALE * cosf(acosf(t) + MARGIN);
        float excl = g_rowsum[b] - __expf(S_SCALE * t);
        double denom = (double)__expf(num) + (double)excl;
        a += (double)num - log(denom);
    }
    sh[threadIdx.x] = a;
    __syncthreads();
    for (int s = 512; s > 0; s >>= 1) {
        if (threadIdx.x < s) sh[threadIdx.x] += sh[threadIdx.x + s];
        __syncthreads();
    }
    if (threadIdx.x == 0) out[0] = (float)(-sh[0] / (double)B_ROWS);
}

// ---------------------------------------------------------------------------
extern "C" void kernel_launch(void* const* d_in, const int* in_sizes, int n_in,
                              void* d_out, int out_size) {
    const float* F = (const float*)d_in[0];
    const int*   Y = (const int*)d_in[1];
    const float* W = (const float*)d_in[2];
    float* out = (float*)d_out;

    cudaFuncSetAttribute(gemm_exp_mma_kernel,
                         cudaFuncAttributeMaxDynamicSharedMemorySize, SMEM_TOTAL);

    prep_kernel<<<PREP_BLOCKS, 256>>>(F, Y, W);

    dim3 grid(C_CLS / BN, B_ROWS / BM);   // (256, 16)
    gemm_exp_mma_kernel<<<grid, 256, SMEM_TOTAL>>>();

    loss_kernel<<<1, 1024>>>(out);
}